// round 12
// baseline (speedup 1.0000x reference)
#include <cuda_runtime.h>
#include <cuda_fp16.h>
#include <cstdint>
#include <cstdio>

// ---------------------------------------------------------------------------
// Problem constants
// ---------------------------------------------------------------------------
#define NROWS 8192
#define FDIM  512
#define HDIM  1024
#define STEPS 50
#define NELEM (NROWS * FDIM)          // 4194304

// ---------------------------------------------------------------------------
// Scratch (device globals: allocation-free rule)
// ---------------------------------------------------------------------------
__device__ float  g_x[NELEM];                 // fp32 diffusion state
__device__ __half g_xh[NELEM];                // fp16 of x (GEMM input)
__device__ __half g_qfh[NROWS * HDIM];
__device__ __half g_h01[NROWS * 2 * HDIM];    // fused [h0 | h1], ld = 2048
__device__ __half g_hh[NROWS * HDIM];         // gelu hidden
__device__ __half g_cath[NROWS * HDIM];       // fp16 cat (GEMM input)
__device__ float  g_catf[NROWS * HDIM];       // fp32 cat (update input)

// transposed fp16 weights (B operands, K-major [N,K])
__device__ __half g_WqT[HDIM * FDIM];
__device__ __half g_W0111T[2 * HDIM * HDIM];  // stacked [W01T ; W11T]
__device__ __half g_W02T[FDIM * HDIM];
__device__ __half g_W12T[FDIM * HDIM];
__device__ __half g_Wi1T[HDIM * HDIM];
__device__ __half g_Wi2T[FDIM * HDIM];

__device__ float g_sp0, g_sp1, g_p0, g_u;
__device__ float g_cA[STEPS], g_rsqa[STEPS], g_qi[STEPS], g_ncoef[STEPS];
__device__ unsigned g_key[STEPS][2];
__device__ unsigned g_key_init[2];

// ---------------------------------------------------------------------------
// PTX helpers (baseline ISA — compute_103 target has no tcgen05)
// ---------------------------------------------------------------------------
__device__ __forceinline__ uint32_t smem_to_u32(const void* p) {
    uint32_t a;
    asm("{ .reg .u64 t; cvta.to.shared.u64 t, %1; cvt.u32.u64 %0, t; }"
        : "=r"(a) : "l"(p));
    return a;
}
__device__ __forceinline__ void cp16(uint32_t dst, const void* src) {
    asm volatile("cp.async.cg.shared.global [%0], [%1], 16;"
                 :: "r"(dst), "l"(src) : "memory");
}
#define CP_COMMIT() asm volatile("cp.async.commit_group;" ::: "memory")
#define LDSM4(R, addr) \
    asm volatile("ldmatrix.sync.aligned.m8n8.x4.shared.b16 {%0,%1,%2,%3}, [%4];" \
                 : "=r"((R)[0]), "=r"((R)[1]), "=r"((R)[2]), "=r"((R)[3]) : "r"(addr))
__device__ __forceinline__ void mma_f16(float* d, const uint32_t* a, const uint32_t* b) {
    asm volatile("mma.sync.aligned.m16n8k16.row.col.f32.f16.f16.f32 "
                 "{%0,%1,%2,%3}, {%4,%5,%6,%7}, {%8,%9}, {%0,%1,%2,%3};"
                 : "+f"(d[0]), "+f"(d[1]), "+f"(d[2]), "+f"(d[3])
                 : "r"(a[0]), "r"(a[1]), "r"(a[2]), "r"(a[3]), "r"(b[0]), "r"(b[1]));
}

// ---------------------------------------------------------------------------
// Threefry-2x32 (JAX partitionable mode)
// ---------------------------------------------------------------------------
__device__ __forceinline__ void tf2x32(unsigned k0, unsigned k1,
                                       unsigned x0, unsigned x1,
                                       unsigned& o0, unsigned& o1) {
    unsigned ks2 = k0 ^ k1 ^ 0x1BD11BDAu;
    x0 += k0; x1 += k1;
#define TF_RND(r) { x0 += x1; x1 = __funnelshift_l(x1, x1, (r)); x1 ^= x0; }
    TF_RND(13) TF_RND(15) TF_RND(26) TF_RND(6)
    x0 += k1;  x1 += ks2 + 1u;
    TF_RND(17) TF_RND(29) TF_RND(16) TF_RND(24)
    x0 += ks2; x1 += k0 + 2u;
    TF_RND(13) TF_RND(15) TF_RND(26) TF_RND(6)
    x0 += k0;  x1 += k1 + 3u;
    TF_RND(17) TF_RND(29) TF_RND(16) TF_RND(24)
    x0 += k1;  x1 += ks2 + 4u;
    TF_RND(13) TF_RND(15) TF_RND(26) TF_RND(6)
    x0 += ks2; x1 += k0 + 5u;
#undef TF_RND
    o0 = x0; o1 = x1;
}
__device__ __forceinline__ unsigned tf_bits(unsigned k0, unsigned k1, unsigned i) {
    unsigned o0, o1;
    tf2x32(k0, k1, 0u, i, o0, o1);
    return o0 ^ o1;
}
__device__ __forceinline__ float bits_to_normal(unsigned b) {
    float u = __uint_as_float((b >> 9) | 0x3f800000u) - 1.0f;
    const float LO = -0.99999994f;
    float v = fmaxf(fmaf(u, 2.0f, LO), LO);
    return 1.41421356f * erfinvf(v);
}

// ---------------------------------------------------------------------------
// Prep: per-step scalars, keys, measurement u
// ---------------------------------------------------------------------------
__global__ void prep_kernel(const float* __restrict__ alpha_amp,
                            const float* __restrict__ beta_amp,
                            const float* __restrict__ phase_cos) {
    int s = threadIdx.x;
    float A = *alpha_amp, B = *beta_amp, pc = *phase_cos;
    float a2 = A * A, b2 = B * B;
    float p0 = a2 / (a2 + b2), p1 = b2 / (a2 + b2);
    if (s == 0) { g_p0 = p0; g_sp0 = sqrtf(p0); g_sp1 = sqrtf(p1); }
    if (s < STEPS) {
        int t = (STEPS - 1) - s;
        const float delta = (0.02f - 1e-4f) / 99.0f;
        float sched_t = 1e-4f + (float)t * delta;
        float alpha = fmaxf(1.0f - sched_t, 1e-8f);
        float alpha_prev = (t > 0) ? (1.0f - (1e-4f + (float)(t - 1) * delta)) : 1.0f;
        float one_m_a = 1.0f - alpha;
        g_cA[s]   = one_m_a / sqrtf(fmaxf(one_m_a, 1e-8f));
        g_rsqa[s] = 1.0f / sqrtf(alpha);
        float decay = expf(-0.1f);
        float coh = 1.0f;
        for (int i = 0; i < s; i++) coh *= decay;
        float qi = 2.0f * sqrtf(p0 * p1) * pc * coh;
        g_qi[s] = qi;
        float sig2 = (1.0f - alpha_prev) / (1.0f - alpha) * (1.0f - alpha / alpha_prev);
        g_ncoef[s] = (t > 0) ? (sqrtf(fmaxf(sig2, 0.0f)) + 0.1f * fabsf(qi)) : 0.0f;
        unsigned o0, o1;
        tf2x32(0u, 1u, 0u, (unsigned)t, o0, o1);
        g_key[s][0] = o0; g_key[s][1] = o1;
    }
    if (s == STEPS) {
        unsigned o0, o1;
        tf2x32(0u, 1u, 0u, 10000u, o0, o1);
        g_key_init[0] = o0; g_key_init[1] = o1;
    }
    if (s == STEPS + 1) {
        unsigned k0, k1;
        tf2x32(0u, 1u, 0u, 99999u, k0, k1);
        unsigned b = tf_bits(k0, k1, 0u);
        g_u = __uint_as_float((b >> 9) | 0x3f800000u) - 1.0f;
    }
}

// ---------------------------------------------------------------------------
// Single merged weight transpose + fp16 convert (7 segments via blockIdx.y)
// ---------------------------------------------------------------------------
__global__ __launch_bounds__(256)
void wprep_all_kernel(const float* __restrict__ Wq,  const float* __restrict__ W01,
                      const float* __restrict__ W11, const float* __restrict__ W02,
                      const float* __restrict__ W12, const float* __restrict__ Wi1,
                      const float* __restrict__ Wi2) {
    int i = blockIdx.x * 256 + threadIdx.x;
    int seg = blockIdx.y;
    const float* src;
    __half* dst;
    int K, N;
    size_t dstoff = 0;
    switch (seg) {
        case 0: src = Wq;  dst = g_WqT;    K = FDIM; N = HDIM; break;
        case 1: src = W01; dst = g_W0111T; K = HDIM; N = HDIM; break;
        case 2: src = W11; dst = g_W0111T; K = HDIM; N = HDIM; dstoff = (size_t)HDIM * HDIM; break;
        case 3: src = W02; dst = g_W02T;   K = HDIM; N = FDIM; break;
        case 4: src = W12; dst = g_W12T;   K = HDIM; N = FDIM; break;
        case 5: src = Wi1; dst = g_Wi1T;   K = HDIM; N = HDIM; break;
        default: src = Wi2; dst = g_Wi2T;  K = HDIM; N = FDIM; break;
    }
    if (i >= K * N) return;
    int k = i / N, n = i - k * N;
    dst[dstoff + (size_t)n * K + k] = __float2half(src[i]);
}

// ---------------------------------------------------------------------------
// x0 init: normal + fp16 copy
// ---------------------------------------------------------------------------
__global__ __launch_bounds__(256) void init_kernel() {
    int j = blockIdx.x * 256 + threadIdx.x;
    float v = bits_to_normal(tf_bits(g_key_init[0], g_key_init[1], (unsigned)j));
    g_x[j] = v;
    g_xh[j] = __float2half(v);
}

// ---------------------------------------------------------------------------
// fp16 HMMA GEMM (mma.sync m16n8k16).
// C = act(A @ B^T + bias);  A [M,*] lda-strided, B [N,Ka] K-major.
// CTA 128(M)x64(N), BK=64, 8 warps (4x2), warp tile 32x32 (2x4 m16n8).
// acc = 32 regs/thread -> ~70 regs total -> 3 CTAs/SM (24 warps, 3 barrier
// domains). 2-stage cp.async, R10 two-sync schedule (proven).
// SMEM stage: A 128x144B (18432) + B 64x144B (9216) = 27648; 2 stages 55296.
// ACT: 0=none 1=relu 2=tanh 3=gelu 4=relu if n0<HDIM else tanh (uses bias2).
// OUTM: 0 = fp16 out, 2 = fp16+fp32 out, 3 = fused diffusion update.
// ---------------------------------------------------------------------------
#define SM_PITCH 144
#define SM_A     (128 * SM_PITCH)           // 18432
#define SM_B     (64 * SM_PITCH)            // 9216
#define SM_STAGE (SM_A + SM_B)              // 27648
#define SMEM_TOTAL (2 * SM_STAGE)           // 55296

template <int ACT, int OUTM>
__global__ __launch_bounds__(256, 3)
void mm_kernel(const __half* __restrict__ A, int lda, int Ka,
               const __half* __restrict__ B,
               const float* __restrict__ bias, const float* __restrict__ bias2,
               __half* __restrict__ Ch, float* __restrict__ Cf,
               int ldc, int col_off, int step) {
    extern __shared__ char smem[];
    const uint32_t sb = smem_to_u32(smem);
    const int tid = threadIdx.x, lane = tid & 31, wid = tid >> 5;
    const int wr = wid >> 1, wc = wid & 1;            // warp grid 4x2
    const int m0 = blockIdx.y * 128, n0 = blockIdx.x * 64;
    const int NC = Ka / 64;

    float acc[2][4][4];
#pragma unroll
    for (int i = 0; i < 2; i++)
#pragma unroll
        for (int j = 0; j < 4; j++)
#pragma unroll
            for (int q = 0; q < 4; q++) acc[i][j][q] = 0.0f;

    auto issue = [&](int c) {
        int k0 = c * 64;
        uint32_t so = sb + (c & 1) * SM_STAGE;
        // A tile: 128 rows x 8 chunks = 1024 slots -> 4/thread
#pragma unroll
        for (int i = 0; i < 4; i++) {
            int idx = tid + i * 256;
            int r = idx >> 3, cc = idx & 7;
            cp16(so + r * SM_PITCH + cc * 16,
                 A + (size_t)(m0 + r) * lda + k0 + cc * 8);
        }
        // B tile: 64 rows x 8 chunks = 512 slots -> 2/thread
#pragma unroll
        for (int i = 0; i < 2; i++) {
            int idx = tid + i * 256;
            int r = idx >> 3, cc = idx & 7;
            cp16(so + SM_A + r * SM_PITCH + cc * 16,
                 B + (size_t)(n0 + r) * Ka + k0 + cc * 8);
        }
        CP_COMMIT();
    };

    issue(0);
    if (NC > 1) issue(1);

    for (int c = 0; c < NC; c++) {
        if (c + 1 < NC) asm volatile("cp.async.wait_group 1;" ::: "memory");
        else            asm volatile("cp.async.wait_group 0;" ::: "memory");
        __syncthreads();

        uint32_t so = sb + (c & 1) * SM_STAGE;
#pragma unroll
        for (int ks = 0; ks < 4; ks++) {
            uint32_t ah[2][4];
            {
                int arow = wr * 32 + (lane & 15);
                uint32_t acol = (uint32_t)(ks * 16 + ((lane >> 4) << 3)) * 2;
#pragma unroll
                for (int mt = 0; mt < 2; mt++)
                    LDSM4(ah[mt], so + (uint32_t)(arow + mt * 16) * SM_PITCH + acol);
            }
            uint32_t bh[2][4];
            {
                int g = lane >> 3;
                int brow = wc * 32 + (lane & 7) + ((g >> 1) << 3);
                uint32_t bcol = (uint32_t)(ks * 16 + ((g & 1) << 3)) * 2;
#pragma unroll
                for (int p = 0; p < 2; p++)
                    LDSM4(bh[p], so + SM_A + (uint32_t)(brow + p * 16) * SM_PITCH + bcol);
            }
#pragma unroll
            for (int mt = 0; mt < 2; mt++)
#pragma unroll
                for (int nt = 0; nt < 4; nt++)
                    mma_f16(acc[mt][nt], ah[mt], &bh[nt >> 1][(nt & 1) * 2]);
        }
        __syncthreads();
        if (c + 2 < NC) issue(c + 2);
    }

    // ---- epilogue ----------------------------------------------------------
    if (OUTM == 3) {
        // Fused diffusion update: acc+bias = interf tile; update x in place.
        const float sp0 = g_sp0, sp1 = g_sp1;
        const float qi = g_qi[step], cAv = g_cA[step];
        const float rsqa = g_rsqa[step], nc = g_ncoef[step];
        const unsigned kk0 = g_key[step][0], kk1 = g_key[step][1];
#pragma unroll
        for (int nt = 0; nt < 4; nt++) {
            int colg = n0 + wc * 32 + nt * 8 + (lane & 3) * 2;   // 0..511
            float b0 = bias[colg], b1 = bias[colg + 1];
#pragma unroll
            for (int mt = 0; mt < 2; mt++) {
                int rb = m0 + wr * 32 + mt * 16 + (lane >> 2);
#pragma unroll
                for (int h = 0; h < 2; h++) {
                    int r = rb + h * 8;
                    float i0 = acc[mt][nt][h * 2 + 0] + b0;
                    float i1 = acc[mt][nt][h * 2 + 1] + b1;
                    size_t cb = (size_t)r * HDIM + colg;
                    float d0a = g_catf[cb],       d0b = g_catf[cb + 1];
                    float d1a = g_catf[cb + 512], d1b = g_catf[cb + 513];
                    int j = r * FDIM + colg;
                    float2 xv = *(float2*)(g_x + j);
                    float xn0 = (xv.x - cAv * (sp0 * d0a + sp1 * d1a + qi * i0)) * rsqa;
                    float xn1 = (xv.y - cAv * (sp0 * d0b + sp1 * d1b + qi * i1)) * rsqa;
                    if (nc != 0.0f) {
                        xn0 += nc * bits_to_normal(tf_bits(kk0, kk1, (unsigned)j));
                        xn1 += nc * bits_to_normal(tf_bits(kk0, kk1, (unsigned)(j + 1)));
                    }
                    *(float2*)(g_x + j) = make_float2(xn0, xn1);
                    *(__half2*)(g_xh + j) = __floats2half2_rn(xn0, xn1);
                }
            }
        }
    } else {
        const bool tanh_side = (ACT == 4) && (n0 >= HDIM);
        const float* bp = (ACT == 4 && tanh_side) ? bias2 : bias;
        const int colbase = (ACT == 4 && tanh_side) ? (n0 - HDIM) : n0;
#pragma unroll
        for (int nt = 0; nt < 4; nt++) {
            int coll = wc * 32 + nt * 8 + (lane & 3) * 2;      // 0..63 in tile
            int colg = n0 + coll;
            float b0 = bp[colbase + coll], b1 = bp[colbase + coll + 1];
#pragma unroll
            for (int mt = 0; mt < 2; mt++) {
                int r0 = m0 + wr * 32 + mt * 16 + (lane >> 2);
                float v[4];
                v[0] = acc[mt][nt][0] + b0;
                v[1] = acc[mt][nt][1] + b1;
                v[2] = acc[mt][nt][2] + b0;
                v[3] = acc[mt][nt][3] + b1;
#pragma unroll
                for (int q = 0; q < 4; q++) {
                    if (ACT == 1) v[q] = fmaxf(v[q], 0.0f);
                    else if (ACT == 2) v[q] = tanhf(v[q]);
                    else if (ACT == 3) v[q] = 0.5f * v[q] * (1.0f + erff(v[q] * 0.70710678f));
                    else if (ACT == 4) v[q] = tanh_side ? tanhf(v[q]) : fmaxf(v[q], 0.0f);
                }
                if (OUTM == 2) {
                    *(float2*)(Cf + (size_t)r0 * ldc + col_off + colg) = make_float2(v[0], v[1]);
                    *(float2*)(Cf + (size_t)(r0 + 8) * ldc + col_off + colg) = make_float2(v[2], v[3]);
                }
                *(__half2*)(Ch + (size_t)r0 * ldc + col_off + colg) = __floats2half2_rn(v[0], v[1]);
                *(__half2*)(Ch + (size_t)(r0 + 8) * ldc + col_off + colg) = __floats2half2_rn(v[2], v[3]);
            }
        }
    }
}

// ---------------------------------------------------------------------------
// Measurement collapse
// ---------------------------------------------------------------------------
__global__ __launch_bounds__(256) void final_kernel(const float* __restrict__ real,
                                                    float* __restrict__ out) {
    int i = blockIdx.x * 256 + threadIdx.x;
    float x = g_x[i];
    out[i] = (g_u < g_p0) ? (0.7f * x + 0.3f * real[i]) : x;
}

// ---------------------------------------------------------------------------
// Launch
// ---------------------------------------------------------------------------
extern "C" void kernel_launch(void* const* d_in, const int* in_sizes, int n_in,
                              void* d_out, int out_size) {
    const float *real, *Wq, *bq, *W01, *b01, *W02, *b02, *W11, *b11;
    const float *W12, *b12, *Wi1, *bi1, *Wi2, *bi2, *a_amp, *b_amp, *pc;

    if (in_sizes[0] == NELEM) {
        int o = (n_in >= 2 && in_sizes[1] == 1) ? 2 : 1;
        real = (const float*)d_in[0];
        Wq   = (const float*)d_in[o + 0];  bq  = (const float*)d_in[o + 1];
        W01  = (const float*)d_in[o + 2];  b01 = (const float*)d_in[o + 3];
        W02  = (const float*)d_in[o + 4];  b02 = (const float*)d_in[o + 5];
        W11  = (const float*)d_in[o + 6];  b11 = (const float*)d_in[o + 7];
        W12  = (const float*)d_in[o + 8];  b12 = (const float*)d_in[o + 9];
        Wi1  = (const float*)d_in[o + 10]; bi1 = (const float*)d_in[o + 11];
        Wi2  = (const float*)d_in[o + 12]; bi2 = (const float*)d_in[o + 13];
        a_amp = (const float*)d_in[o + 14];
        b_amp = (const float*)d_in[o + 15];
        pc    = (const float*)d_in[o + 16];
    } else {
        W01 = (const float*)d_in[0];  W02 = (const float*)d_in[1];
        W11 = (const float*)d_in[2];  W12 = (const float*)d_in[3];
        Wi1 = (const float*)d_in[4];  Wi2 = (const float*)d_in[5];
        Wq  = (const float*)d_in[6];  a_amp = (const float*)d_in[7];
        b01 = (const float*)d_in[8];  b02 = (const float*)d_in[9];
        b11 = (const float*)d_in[10]; b12 = (const float*)d_in[11];
        b_amp = (const float*)d_in[12];
        bi1 = (const float*)d_in[13]; bi2 = (const float*)d_in[14];
        bq  = (const float*)d_in[15]; pc  = (const float*)d_in[16];
        real = (const float*)d_in[17];
    }
    float* out = (float*)d_out;

    void *p;
    #define SYMH(var, sym) cudaGetSymbolAddress(&p, sym); auto* var = (__half*)p;
    SYMH(xh, g_xh)
    SYMH(qfh, g_qfh)
    SYMH(h01, g_h01)
    SYMH(hh, g_hh)
    SYMH(cath, g_cath)
    SYMH(WqT, g_WqT)
    SYMH(W0111T, g_W0111T)
    SYMH(W02T, g_W02T)
    SYMH(W12T, g_W12T)
    SYMH(Wi1T, g_Wi1T)
    SYMH(Wi2T, g_Wi2T)
    #undef SYMH
    cudaGetSymbolAddress(&p, g_catf);   float* catf = (float*)p;

    cudaFuncSetAttribute(mm_kernel<1, 0>, cudaFuncAttributeMaxDynamicSharedMemorySize, SMEM_TOTAL);
    cudaFuncSetAttribute(mm_kernel<4, 0>, cudaFuncAttributeMaxDynamicSharedMemorySize, SMEM_TOTAL);
    cudaFuncSetAttribute(mm_kernel<3, 0>, cudaFuncAttributeMaxDynamicSharedMemorySize, SMEM_TOTAL);
    cudaFuncSetAttribute(mm_kernel<0, 2>, cudaFuncAttributeMaxDynamicSharedMemorySize, SMEM_TOTAL);
    cudaFuncSetAttribute(mm_kernel<0, 3>, cudaFuncAttributeMaxDynamicSharedMemorySize, SMEM_TOTAL);

    prep_kernel<<<1, 64>>>(a_amp, b_amp, pc);
    init_kernel<<<NELEM / 256, 256>>>();
    wprep_all_kernel<<<dim3(4096, 7), 256>>>(Wq, W01, W11, W02, W12, Wi1, Wi2);

    dim3 gH(HDIM / 64, NROWS / 128);         // (16, 64)
    dim3 gH2(2 * HDIM / 64, NROWS / 128);    // (32, 64) fused h01
    dim3 gF(FDIM / 64, NROWS / 128);         // (8, 64)

    for (int s = 0; s < STEPS; s++) {
        // qf = relu(x @ Wq + bq)
        mm_kernel<1, 0><<<gH, 256, SMEM_TOTAL>>>(xh, FDIM, FDIM, WqT, bq, bq,
                                                 qfh, nullptr, HDIM, 0, 0);
        // [h0|h1] = {relu|tanh}(qf @ [W01;W11]^T + {b01|b11})
        mm_kernel<4, 0><<<gH2, 256, SMEM_TOTAL>>>(qfh, HDIM, HDIM, W0111T, b01, b11,
                                                  h01, nullptr, 2 * HDIM, 0, 0);
        // d0 = h0 @ W02 + b02 -> cat[:, 0:512] (fp16 + fp32)
        mm_kernel<0, 2><<<gF, 256, SMEM_TOTAL>>>(h01, 2 * HDIM, HDIM, W02T, b02, b02,
                                                 cath, catf, HDIM, 0, 0);
        // d1 = h1 @ W12 + b12 -> cat[:, 512:1024] (fp16 + fp32)
        mm_kernel<0, 2><<<gF, 256, SMEM_TOTAL>>>(h01 + HDIM, 2 * HDIM, HDIM, W12T, b12, b12,
                                                 cath, catf, HDIM, FDIM, 0);
        // hg = gelu(cat @ Wi1 + bi1)
        mm_kernel<3, 0><<<gH, 256, SMEM_TOTAL>>>(cath, HDIM, HDIM, Wi1T, bi1, bi1,
                                                 hh, nullptr, HDIM, 0, 0);
        // interf GEMM + FUSED diffusion update (writes g_x / g_xh)
        mm_kernel<0, 3><<<gF, 256, SMEM_TOTAL>>>(hh, HDIM, HDIM, Wi2T, bi2, bi2,
                                                 nullptr, nullptr, FDIM, 0, s);
    }

    final_kernel<<<NELEM / 256, 256>>>(real, out);
}

// round 13
// speedup vs baseline: 1.0215x; 1.0215x over previous
#include <cuda_runtime.h>
#include <cuda_fp16.h>
#include <cstdint>
#include <cstdio>

// ---------------------------------------------------------------------------
// Problem constants
// ---------------------------------------------------------------------------
#define NROWS 8192
#define FDIM  512
#define HDIM  1024
#define STEPS 50
#define NELEM (NROWS * FDIM)          // 4194304

// ---------------------------------------------------------------------------
// Scratch (device globals: allocation-free rule)
// ---------------------------------------------------------------------------
__device__ float  g_x[NELEM];                 // fp32 diffusion state
__device__ __half g_xh[NELEM];                // fp16 of x (GEMM input)
__device__ __half g_qfh[NROWS * HDIM];
__device__ __half g_h01[NROWS * 2 * HDIM];    // fused [h0 | h1], ld = 2048
__device__ __half g_hh[NROWS * HDIM];         // gelu hidden
__device__ __half g_cath[NROWS * HDIM];       // fp16 cat (GEMM input)
__device__ float  g_catf[NROWS * HDIM];       // fp32 cat (update input)
__device__ float  g_interf[NELEM];

// transposed fp16 weights (B operands, K-major [N,K])
__device__ __half g_WqT[HDIM * FDIM];
__device__ __half g_W0111T[2 * HDIM * HDIM];  // stacked [W01T ; W11T]
__device__ __half g_W02T[FDIM * HDIM];
__device__ __half g_W12T[FDIM * HDIM];
__device__ __half g_Wi1T[HDIM * HDIM];
__device__ __half g_Wi2T[FDIM * HDIM];

__device__ float g_sp0, g_sp1, g_p0, g_u;
__device__ float g_cA[STEPS], g_rsqa[STEPS], g_qi[STEPS], g_ncoef[STEPS];
__device__ unsigned g_key[STEPS][2];
__device__ unsigned g_key_init[2];

// ---------------------------------------------------------------------------
// PTX helpers (baseline ISA — compute_103 target has no tcgen05)
// ---------------------------------------------------------------------------
__device__ __forceinline__ uint32_t smem_to_u32(const void* p) {
    uint32_t a;
    asm("{ .reg .u64 t; cvta.to.shared.u64 t, %1; cvt.u32.u64 %0, t; }"
        : "=r"(a) : "l"(p));
    return a;
}
__device__ __forceinline__ void cp16(uint32_t dst, const void* src) {
    asm volatile("cp.async.cg.shared.global [%0], [%1], 16;"
                 :: "r"(dst), "l"(src) : "memory");
}
#define CP_COMMIT() asm volatile("cp.async.commit_group;" ::: "memory")
#define LDSM4(R, addr) \
    asm volatile("ldmatrix.sync.aligned.m8n8.x4.shared.b16 {%0,%1,%2,%3}, [%4];" \
                 : "=r"((R)[0]), "=r"((R)[1]), "=r"((R)[2]), "=r"((R)[3]) : "r"(addr))
__device__ __forceinline__ void mma_f16(float* d, const uint32_t* a, const uint32_t* b) {
    asm volatile("mma.sync.aligned.m16n8k16.row.col.f32.f16.f16.f32 "
                 "{%0,%1,%2,%3}, {%4,%5,%6,%7}, {%8,%9}, {%0,%1,%2,%3};"
                 : "+f"(d[0]), "+f"(d[1]), "+f"(d[2]), "+f"(d[3])
                 : "r"(a[0]), "r"(a[1]), "r"(a[2]), "r"(a[3]), "r"(b[0]), "r"(b[1]));
}

// ---------------------------------------------------------------------------
// Threefry-2x32 (JAX partitionable mode)
// ---------------------------------------------------------------------------
__device__ __forceinline__ void tf2x32(unsigned k0, unsigned k1,
                                       unsigned x0, unsigned x1,
                                       unsigned& o0, unsigned& o1) {
    unsigned ks2 = k0 ^ k1 ^ 0x1BD11BDAu;
    x0 += k0; x1 += k1;
#define TF_RND(r) { x0 += x1; x1 = __funnelshift_l(x1, x1, (r)); x1 ^= x0; }
    TF_RND(13) TF_RND(15) TF_RND(26) TF_RND(6)
    x0 += k1;  x1 += ks2 + 1u;
    TF_RND(17) TF_RND(29) TF_RND(16) TF_RND(24)
    x0 += ks2; x1 += k0 + 2u;
    TF_RND(13) TF_RND(15) TF_RND(26) TF_RND(6)
    x0 += k0;  x1 += k1 + 3u;
    TF_RND(17) TF_RND(29) TF_RND(16) TF_RND(24)
    x0 += k1;  x1 += ks2 + 4u;
    TF_RND(13) TF_RND(15) TF_RND(26) TF_RND(6)
    x0 += ks2; x1 += k0 + 5u;
#undef TF_RND
    o0 = x0; o1 = x1;
}
__device__ __forceinline__ unsigned tf_bits(unsigned k0, unsigned k1, unsigned i) {
    unsigned o0, o1;
    tf2x32(k0, k1, 0u, i, o0, o1);
    return o0 ^ o1;
}
__device__ __forceinline__ float bits_to_normal(unsigned b) {
    float u = __uint_as_float((b >> 9) | 0x3f800000u) - 1.0f;
    const float LO = -0.99999994f;
    float v = fmaxf(fmaf(u, 2.0f, LO), LO);
    return 1.41421356f * erfinvf(v);
}

// ---------------------------------------------------------------------------
// Prep: per-step scalars, keys, measurement u
// ---------------------------------------------------------------------------
__global__ void prep_kernel(const float* __restrict__ alpha_amp,
                            const float* __restrict__ beta_amp,
                            const float* __restrict__ phase_cos) {
    int s = threadIdx.x;
    float A = *alpha_amp, B = *beta_amp, pc = *phase_cos;
    float a2 = A * A, b2 = B * B;
    float p0 = a2 / (a2 + b2), p1 = b2 / (a2 + b2);
    if (s == 0) { g_p0 = p0; g_sp0 = sqrtf(p0); g_sp1 = sqrtf(p1); }
    if (s < STEPS) {
        int t = (STEPS - 1) - s;
        const float delta = (0.02f - 1e-4f) / 99.0f;
        float sched_t = 1e-4f + (float)t * delta;
        float alpha = fmaxf(1.0f - sched_t, 1e-8f);
        float alpha_prev = (t > 0) ? (1.0f - (1e-4f + (float)(t - 1) * delta)) : 1.0f;
        float one_m_a = 1.0f - alpha;
        g_cA[s]   = one_m_a / sqrtf(fmaxf(one_m_a, 1e-8f));
        g_rsqa[s] = 1.0f / sqrtf(alpha);
        float decay = expf(-0.1f);
        float coh = 1.0f;
        for (int i = 0; i < s; i++) coh *= decay;
        float qi = 2.0f * sqrtf(p0 * p1) * pc * coh;
        g_qi[s] = qi;
        float sig2 = (1.0f - alpha_prev) / (1.0f - alpha) * (1.0f - alpha / alpha_prev);
        g_ncoef[s] = (t > 0) ? (sqrtf(fmaxf(sig2, 0.0f)) + 0.1f * fabsf(qi)) : 0.0f;
        unsigned o0, o1;
        tf2x32(0u, 1u, 0u, (unsigned)t, o0, o1);
        g_key[s][0] = o0; g_key[s][1] = o1;
    }
    if (s == STEPS) {
        unsigned o0, o1;
        tf2x32(0u, 1u, 0u, 10000u, o0, o1);
        g_key_init[0] = o0; g_key_init[1] = o1;
    }
    if (s == STEPS + 1) {
        unsigned k0, k1;
        tf2x32(0u, 1u, 0u, 99999u, k0, k1);
        unsigned b = tf_bits(k0, k1, 0u);
        g_u = __uint_as_float((b >> 9) | 0x3f800000u) - 1.0f;
    }
}

// ---------------------------------------------------------------------------
// Single merged weight transpose + fp16 convert (7 segments via blockIdx.y)
// ---------------------------------------------------------------------------
__global__ __launch_bounds__(256)
void wprep_all_kernel(const float* __restrict__ Wq,  const float* __restrict__ W01,
                      const float* __restrict__ W11, const float* __restrict__ W02,
                      const float* __restrict__ W12, const float* __restrict__ Wi1,
                      const float* __restrict__ Wi2) {
    int i = blockIdx.x * 256 + threadIdx.x;
    int seg = blockIdx.y;
    const float* src;
    __half* dst;
    int K, N;
    size_t dstoff = 0;
    switch (seg) {
        case 0: src = Wq;  dst = g_WqT;    K = FDIM; N = HDIM; break;
        case 1: src = W01; dst = g_W0111T; K = HDIM; N = HDIM; break;
        case 2: src = W11; dst = g_W0111T; K = HDIM; N = HDIM; dstoff = (size_t)HDIM * HDIM; break;
        case 3: src = W02; dst = g_W02T;   K = HDIM; N = FDIM; break;
        case 4: src = W12; dst = g_W12T;   K = HDIM; N = FDIM; break;
        case 5: src = Wi1; dst = g_Wi1T;   K = HDIM; N = HDIM; break;
        default: src = Wi2; dst = g_Wi2T;  K = HDIM; N = FDIM; break;
    }
    if (i >= K * N) return;
    int k = i / N, n = i - k * N;
    dst[dstoff + (size_t)n * K + k] = __float2half(src[i]);
}

// ---------------------------------------------------------------------------
// x0 init: normal + fp16 copy
// ---------------------------------------------------------------------------
__global__ __launch_bounds__(256) void init_kernel() {
    int j = blockIdx.x * 256 + threadIdx.x;
    float v = bits_to_normal(tf_bits(g_key_init[0], g_key_init[1], (unsigned)j));
    g_x[j] = v;
    g_xh[j] = __float2half(v);
}

// ---------------------------------------------------------------------------
// fp16 HMMA GEMM (mma.sync m16n8k16) with EXPLICIT fragment double-buffering.
// C = act(A @ B^T + bias);  A [M,*] lda-strided, B [N,Ka] K-major.
// CTA 128x128, BK=64, 8 warps (2x4), warp tile 64x32.
// 3-stage cp.async, single sync per chunk; fragments for ks+1 are loaded
// BEFORE the MMAs of ks issue (intra-warp latency hiding; ~160 regs, 1 CTA/SM).
// Dual-GEMM: when gridDim.z==2, blockIdx.z==1 switches to (A2,B2,bias2,col_off2).
// ACT: 0=none 1=relu 2=tanh 3=gelu 4=relu if n0<HDIM else tanh (bias2 = b11).
// OUTM: 0 = fp16 out, 1 = fp32 out, 2 = fp16+fp32 out.
// ---------------------------------------------------------------------------
#define SM_PITCH 144
#define SM_HALF  (128 * SM_PITCH)           // 18432
#define SM_STAGE (2 * SM_HALF)              // 36864
#define SMEM_TOTAL (3 * SM_STAGE)           // 110592

template <int ACT, int OUTM>
__global__ __launch_bounds__(256)
void mm_kernel(const __half* __restrict__ A, int lda, int Ka,
               const __half* __restrict__ B,
               const float* __restrict__ bias, const float* __restrict__ bias2,
               __half* __restrict__ Ch, float* __restrict__ Cf,
               int ldc, int col_off,
               const __half* __restrict__ A2, const __half* __restrict__ B2,
               int col_off2) {
    extern __shared__ char smem[];
    const uint32_t sb = smem_to_u32(smem);
    const int tid = threadIdx.x, lane = tid & 31, wid = tid >> 5;
    const int wr = wid >> 2, wc = wid & 3;            // warp grid 2x4
    const int m0 = blockIdx.y * 128, n0 = blockIdx.x * 128;
    const int NC = Ka / 64;

    if (blockIdx.z == 1) {        // dual-GEMM second problem
        A = A2; B = B2; bias = bias2; col_off = col_off2;
    }

    float acc[4][4][4];
#pragma unroll
    for (int i = 0; i < 4; i++)
#pragma unroll
        for (int j = 0; j < 4; j++)
#pragma unroll
            for (int q = 0; q < 4; q++) acc[i][j][q] = 0.0f;

    auto issue = [&](int c) {
        int k0 = c * 64;
        uint32_t so = sb + (c % 3) * SM_STAGE;
#pragma unroll
        for (int i = 0; i < 4; i++) {
            int idx = tid + i * 256;              // 0..1023
            int r = idx >> 3, cc = idx & 7;       // row, 16B chunk
            uint32_t d = so + r * SM_PITCH + cc * 16;
            cp16(d,           A + (size_t)(m0 + r) * lda + k0 + cc * 8);
            cp16(d + SM_HALF, B + (size_t)(n0 + r) * Ka  + k0 + cc * 8);
        }
        CP_COMMIT();
    };

    // fragment loader for one ks (0..3) within the stage at smem offset so
    const int arow = wr * 64 + (lane & 15);
    const uint32_t acolbase = (uint32_t)((lane >> 4) << 3) * 2;
    const int bg = lane >> 3;
    const int brow = wc * 32 + (lane & 7) + ((bg >> 1) << 3);
    const uint32_t bcolbase = (uint32_t)((bg & 1) << 3) * 2;

    auto ldfrags = [&](uint32_t so, int ks, uint32_t ah[4][4], uint32_t bh[2][4]) {
        uint32_t acol = acolbase + (uint32_t)(ks * 32);
        uint32_t bcol = bcolbase + (uint32_t)(ks * 32);
#pragma unroll
        for (int mt = 0; mt < 4; mt++)
            LDSM4(ah[mt], so + (uint32_t)(arow + mt * 16) * SM_PITCH + acol);
#pragma unroll
        for (int p = 0; p < 2; p++)
            LDSM4(bh[p], so + SM_HALF + (uint32_t)(brow + p * 16) * SM_PITCH + bcol);
    };

    issue(0);
    if (NC > 1) issue(1);

    uint32_t ah[2][4][4], bh[2][2][4];

    for (int c = 0; c < NC; c++) {
        if (c + 1 < NC) asm volatile("cp.async.wait_group 1;" ::: "memory");
        else            asm volatile("cp.async.wait_group 0;" ::: "memory");
        __syncthreads();
        if (c + 2 < NC) issue(c + 2);          // stage (c+2)%3 freed at iter c-1

        uint32_t so = sb + (c % 3) * SM_STAGE;
        ldfrags(so, 0, ah[0], bh[0]);          // prime ks=0
#pragma unroll
        for (int ks = 0; ks < 4; ks++) {
            int cur = ks & 1, nxt = cur ^ 1;
            if (ks < 3) ldfrags(so, ks + 1, ah[nxt], bh[nxt]);   // hoist above MMAs
#pragma unroll
            for (int mt = 0; mt < 4; mt++)
#pragma unroll
                for (int nt = 0; nt < 4; nt++)
                    mma_f16(acc[mt][nt], ah[cur][mt], &bh[cur][nt >> 1][(nt & 1) * 2]);
        }
    }

    // ---- epilogue ----------------------------------------------------------
    const bool tanh_side = (ACT == 4) && (n0 >= HDIM);
    const float* bp = (ACT == 4 && tanh_side) ? bias2 : bias;
    const int colbase = (ACT == 4 && tanh_side) ? (n0 - HDIM) : n0;
#pragma unroll
    for (int nt = 0; nt < 4; nt++) {
        int coll = wc * 32 + nt * 8 + (lane & 3) * 2;
        int colg = n0 + coll;
        float b0 = bp[colbase + coll], b1 = bp[colbase + coll + 1];
#pragma unroll
        for (int mt = 0; mt < 4; mt++) {
            int r0 = m0 + wr * 64 + mt * 16 + (lane >> 2);
            float v[4];
            v[0] = acc[mt][nt][0] + b0;
            v[1] = acc[mt][nt][1] + b1;
            v[2] = acc[mt][nt][2] + b0;
            v[3] = acc[mt][nt][3] + b1;
#pragma unroll
            for (int q = 0; q < 4; q++) {
                if (ACT == 1) v[q] = fmaxf(v[q], 0.0f);
                else if (ACT == 2) v[q] = tanhf(v[q]);
                else if (ACT == 3) v[q] = 0.5f * v[q] * (1.0f + erff(v[q] * 0.70710678f));
                else if (ACT == 4) v[q] = tanh_side ? tanhf(v[q]) : fmaxf(v[q], 0.0f);
            }
            if (OUTM != 0) {
                *(float2*)(Cf + (size_t)r0 * ldc + col_off + colg) = make_float2(v[0], v[1]);
                *(float2*)(Cf + (size_t)(r0 + 8) * ldc + col_off + colg) = make_float2(v[2], v[3]);
            }
            if (OUTM != 1) {
                *(__half2*)(Ch + (size_t)r0 * ldc + col_off + colg) = __floats2half2_rn(v[0], v[1]);
                *(__half2*)(Ch + (size_t)(r0 + 8) * ldc + col_off + colg) = __floats2half2_rn(v[2], v[3]);
            }
        }
    }
}

// ---------------------------------------------------------------------------
// Fused diffusion update + Threefry noise (fp32 path; writes x + fp16 copy)
// ---------------------------------------------------------------------------
__global__ __launch_bounds__(256) void update_kernel(int s) {
    int j = blockIdx.x * 256 + threadIdx.x;
    float sp0 = g_sp0, sp1 = g_sp1;
    float qi = g_qi[s], cA = g_cA[s], rsqa = g_rsqa[s], nc = g_ncoef[s];

    int row = j >> 9, col = j & 511;
    int base = (row << 10) + col;
    float d0 = g_catf[base];
    float d1 = g_catf[base + 512];
    float den = sp0 * d0 + sp1 * d1 + qi * g_interf[j];
    float xn = (g_x[j] - cA * den) * rsqa;
    if (nc != 0.0f)
        xn += nc * bits_to_normal(tf_bits(g_key[s][0], g_key[s][1], (unsigned)j));
    g_x[j] = xn;
    g_xh[j] = __float2half(xn);
}

__global__ __launch_bounds__(256) void final_kernel(const float* __restrict__ real,
                                                    float* __restrict__ out) {
    int i = blockIdx.x * 256 + threadIdx.x;
    float x = g_x[i];
    out[i] = (g_u < g_p0) ? (0.7f * x + 0.3f * real[i]) : x;
}

// ---------------------------------------------------------------------------
// Launch
// ---------------------------------------------------------------------------
extern "C" void kernel_launch(void* const* d_in, const int* in_sizes, int n_in,
                              void* d_out, int out_size) {
    const float *real, *Wq, *bq, *W01, *b01, *W02, *b02, *W11, *b11;
    const float *W12, *b12, *Wi1, *bi1, *Wi2, *bi2, *a_amp, *b_amp, *pc;

    if (in_sizes[0] == NELEM) {
        int o = (n_in >= 2 && in_sizes[1] == 1) ? 2 : 1;
        real = (const float*)d_in[0];
        Wq   = (const float*)d_in[o + 0];  bq  = (const float*)d_in[o + 1];
        W01  = (const float*)d_in[o + 2];  b01 = (const float*)d_in[o + 3];
        W02  = (const float*)d_in[o + 4];  b02 = (const float*)d_in[o + 5];
        W11  = (const float*)d_in[o + 6];  b11 = (const float*)d_in[o + 7];
        W12  = (const float*)d_in[o + 8];  b12 = (const float*)d_in[o + 9];
        Wi1  = (const float*)d_in[o + 10]; bi1 = (const float*)d_in[o + 11];
        Wi2  = (const float*)d_in[o + 12]; bi2 = (const float*)d_in[o + 13];
        a_amp = (const float*)d_in[o + 14];
        b_amp = (const float*)d_in[o + 15];
        pc    = (const float*)d_in[o + 16];
    } else {
        W01 = (const float*)d_in[0];  W02 = (const float*)d_in[1];
        W11 = (const float*)d_in[2];  W12 = (const float*)d_in[3];
        Wi1 = (const float*)d_in[4];  Wi2 = (const float*)d_in[5];
        Wq  = (const float*)d_in[6];  a_amp = (const float*)d_in[7];
        b01 = (const float*)d_in[8];  b02 = (const float*)d_in[9];
        b11 = (const float*)d_in[10]; b12 = (const float*)d_in[11];
        b_amp = (const float*)d_in[12];
        bi1 = (const float*)d_in[13]; bi2 = (const float*)d_in[14];
        bq  = (const float*)d_in[15]; pc  = (const float*)d_in[16];
        real = (const float*)d_in[17];
    }
    float* out = (float*)d_out;

    void *p;
    #define SYMH(var, sym) cudaGetSymbolAddress(&p, sym); auto* var = (__half*)p;
    SYMH(xh, g_xh)
    SYMH(qfh, g_qfh)
    SYMH(h01, g_h01)
    SYMH(hh, g_hh)
    SYMH(cath, g_cath)
    SYMH(WqT, g_WqT)
    SYMH(W0111T, g_W0111T)
    SYMH(W02T, g_W02T)
    SYMH(W12T, g_W12T)
    SYMH(Wi1T, g_Wi1T)
    SYMH(Wi2T, g_Wi2T)
    #undef SYMH
    cudaGetSymbolAddress(&p, g_catf);   float* catf = (float*)p;
    cudaGetSymbolAddress(&p, g_interf); float* itf  = (float*)p;

    cudaFuncSetAttribute(mm_kernel<1, 0>, cudaFuncAttributeMaxDynamicSharedMemorySize, SMEM_TOTAL);
    cudaFuncSetAttribute(mm_kernel<4, 0>, cudaFuncAttributeMaxDynamicSharedMemorySize, SMEM_TOTAL);
    cudaFuncSetAttribute(mm_kernel<3, 0>, cudaFuncAttributeMaxDynamicSharedMemorySize, SMEM_TOTAL);
    cudaFuncSetAttribute(mm_kernel<0, 2>, cudaFuncAttributeMaxDynamicSharedMemorySize, SMEM_TOTAL);
    cudaFuncSetAttribute(mm_kernel<0, 1>, cudaFuncAttributeMaxDynamicSharedMemorySize, SMEM_TOTAL);

    prep_kernel<<<1, 64>>>(a_amp, b_amp, pc);
    init_kernel<<<NELEM / 256, 256>>>();
    wprep_all_kernel<<<dim3(4096, 7), 256>>>(Wq, W01, W11, W02, W12, Wi1, Wi2);

    dim3 gH(HDIM / 128, NROWS / 128);          // (8, 64)
    dim3 gH2(2 * HDIM / 128, NROWS / 128);     // (16, 64) fused h01
    dim3 gFz(FDIM / 128, NROWS / 128, 2);      // (4, 64, 2) dual d0/d1
    dim3 gF(FDIM / 128, NROWS / 128);          // (4, 64)

    for (int s = 0; s < STEPS; s++) {
        // qf = relu(x @ Wq + bq)
        mm_kernel<1, 0><<<gH, 256, SMEM_TOTAL>>>(xh, FDIM, FDIM, WqT, bq, bq,
                                                 qfh, nullptr, HDIM, 0,
                                                 nullptr, nullptr, 0);
        // [h0|h1] = {relu|tanh}(qf @ [W01;W11]^T + {b01|b11})
        mm_kernel<4, 0><<<gH2, 256, SMEM_TOTAL>>>(qfh, HDIM, HDIM, W0111T, b01, b11,
                                                  h01, nullptr, 2 * HDIM, 0,
                                                  nullptr, nullptr, 0);
        // dual: z=0 -> d0 = h0 @ W02 + b02 -> cat[:,0:512]
        //       z=1 -> d1 = h1 @ W12 + b12 -> cat[:,512:1024]   (fp16 + fp32)
        mm_kernel<0, 2><<<gFz, 256, SMEM_TOTAL>>>(h01, 2 * HDIM, HDIM, W02T, b02, b12,
                                                  cath, catf, HDIM, 0,
                                                  h01 + HDIM, W12T, FDIM);
        // hg = gelu(cat @ Wi1 + bi1)
        mm_kernel<3, 0><<<gH, 256, SMEM_TOTAL>>>(cath, HDIM, HDIM, Wi1T, bi1, bi1,
                                                 hh, nullptr, HDIM, 0,
                                                 nullptr, nullptr, 0);
        // interf = hg @ Wi2 + bi2  (fp32 out)
        mm_kernel<0, 1><<<gF, 256, SMEM_TOTAL>>>(hh, HDIM, HDIM, Wi2T, bi2, bi2,
                                                 nullptr, itf, FDIM, 0,
                                                 nullptr, nullptr, 0);
        // diffusion update + noise
        update_kernel<<<NELEM / 256, 256>>>(s);
    }

    final_kernel<<<NELEM / 256, 256>>>(real, out);
}

// round 16
// speedup vs baseline: 1.0715x; 1.0489x over previous
#include <cuda_runtime.h>
#include <cuda_fp16.h>
#include <cstdint>
#include <cstdio>

// ---------------------------------------------------------------------------
// Problem constants
// ---------------------------------------------------------------------------
#define NROWS 8192
#define FDIM  512
#define HDIM  1024
#define STEPS 50
#define NELEM (NROWS * FDIM)          // 4194304

// ---------------------------------------------------------------------------
// Scratch (device globals: allocation-free rule)
// ---------------------------------------------------------------------------
__device__ float  g_x[NELEM];                 // fp32 diffusion state
__device__ __half g_xh[NELEM];                // fp16 of x (GEMM input)
__device__ __half g_qfh[NROWS * HDIM];
__device__ __half g_h01[NROWS * 2 * HDIM];    // fused [h0 | h1], ld = 2048
__device__ __half g_hh[NROWS * HDIM];         // gelu hidden
__device__ __half g_cath[NROWS * HDIM];       // fp16 cat [d0 | d1]

// transposed fp16 weights (B operands, K-major [N,K])
__device__ __half g_WqT[HDIM * FDIM];
__device__ __half g_W0111T[2 * HDIM * HDIM];  // stacked [W01T ; W11T]
__device__ __half g_W02T[FDIM * HDIM];
__device__ __half g_W12T[FDIM * HDIM];
__device__ __half g_Wi1T[HDIM * HDIM];
__device__ __half g_Wi2T[FDIM * HDIM];

__device__ float g_sp0, g_sp1, g_p0, g_u;
__device__ float g_cA[STEPS], g_rsqa[STEPS], g_qi[STEPS], g_ncoef[STEPS];
__device__ unsigned g_key[STEPS][2];
__device__ unsigned g_key_init[2];

// ---------------------------------------------------------------------------
// PTX helpers (baseline ISA — compute_103 target has no tcgen05)
// ---------------------------------------------------------------------------
__device__ __forceinline__ uint32_t smem_to_u32(const void* p) {
    uint32_t a;
    asm("{ .reg .u64 t; cvta.to.shared.u64 t, %1; cvt.u32.u64 %0, t; }"
        : "=r"(a) : "l"(p));
    return a;
}
__device__ __forceinline__ void cp16(uint32_t dst, const void* src) {
    asm volatile("cp.async.cg.shared.global [%0], [%1], 16;"
                 :: "r"(dst), "l"(src) : "memory");
}
#define CP_COMMIT() asm volatile("cp.async.commit_group;" ::: "memory")
#define LDSM4(R, addr) \
    asm volatile("ldmatrix.sync.aligned.m8n8.x4.shared.b16 {%0,%1,%2,%3}, [%4];" \
                 : "=r"((R)[0]), "=r"((R)[1]), "=r"((R)[2]), "=r"((R)[3]) : "r"(addr))
__device__ __forceinline__ void mma_f16(float* d, const uint32_t* a, const uint32_t* b) {
    asm volatile("mma.sync.aligned.m16n8k16.row.col.f32.f16.f16.f32 "
                 "{%0,%1,%2,%3}, {%4,%5,%6,%7}, {%8,%9}, {%0,%1,%2,%3};"
                 : "+f"(d[0]), "+f"(d[1]), "+f"(d[2]), "+f"(d[3])
                 : "r"(a[0]), "r"(a[1]), "r"(a[2]), "r"(a[3]), "r"(b[0]), "r"(b[1]));
}

// ---------------------------------------------------------------------------
// Threefry-2x32 (JAX partitionable mode)
// ---------------------------------------------------------------------------
__device__ __forceinline__ void tf2x32(unsigned k0, unsigned k1,
                                       unsigned x0, unsigned x1,
                                       unsigned& o0, unsigned& o1) {
    unsigned ks2 = k0 ^ k1 ^ 0x1BD11BDAu;
    x0 += k0; x1 += k1;
#define TF_RND(r) { x0 += x1; x1 = __funnelshift_l(x1, x1, (r)); x1 ^= x0; }
    TF_RND(13) TF_RND(15) TF_RND(26) TF_RND(6)
    x0 += k1;  x1 += ks2 + 1u;
    TF_RND(17) TF_RND(29) TF_RND(16) TF_RND(24)
    x0 += ks2; x1 += k0 + 2u;
    TF_RND(13) TF_RND(15) TF_RND(26) TF_RND(6)
    x0 += k0;  x1 += k1 + 3u;
    TF_RND(17) TF_RND(29) TF_RND(16) TF_RND(24)
    x0 += k1;  x1 += ks2 + 4u;
    TF_RND(13) TF_RND(15) TF_RND(26) TF_RND(6)
    x0 += ks2; x1 += k0 + 5u;
#undef TF_RND
    o0 = x0; o1 = x1;
}
__device__ __forceinline__ unsigned tf_bits(unsigned k0, unsigned k1, unsigned i) {
    unsigned o0, o1;
    tf2x32(k0, k1, 0u, i, o0, o1);
    return o0 ^ o1;
}
__device__ __forceinline__ float bits_to_normal(unsigned b) {
    float u = __uint_as_float((b >> 9) | 0x3f800000u) - 1.0f;
    const float LO = -0.99999994f;
    float v = fmaxf(fmaf(u, 2.0f, LO), LO);
    return 1.41421356f * erfinvf(v);
}

// ---------------------------------------------------------------------------
// Prep: per-step scalars, keys, measurement u
// ---------------------------------------------------------------------------
__global__ void prep_kernel(const float* __restrict__ alpha_amp,
                            const float* __restrict__ beta_amp,
                            const float* __restrict__ phase_cos) {
    int s = threadIdx.x;
    float A = *alpha_amp, B = *beta_amp, pc = *phase_cos;
    float a2 = A * A, b2 = B * B;
    float p0 = a2 / (a2 + b2), p1 = b2 / (a2 + b2);
    if (s == 0) { g_p0 = p0; g_sp0 = sqrtf(p0); g_sp1 = sqrtf(p1); }
    if (s < STEPS) {
        int t = (STEPS - 1) - s;
        const float delta = (0.02f - 1e-4f) / 99.0f;
        float sched_t = 1e-4f + (float)t * delta;
        float alpha = fmaxf(1.0f - sched_t, 1e-8f);
        float alpha_prev = (t > 0) ? (1.0f - (1e-4f + (float)(t - 1) * delta)) : 1.0f;
        float one_m_a = 1.0f - alpha;
        g_cA[s]   = one_m_a / sqrtf(fmaxf(one_m_a, 1e-8f));
        g_rsqa[s] = 1.0f / sqrtf(alpha);
        float decay = expf(-0.1f);
        float coh = 1.0f;
        for (int i = 0; i < s; i++) coh *= decay;
        float qi = 2.0f * sqrtf(p0 * p1) * pc * coh;
        g_qi[s] = qi;
        float sig2 = (1.0f - alpha_prev) / (1.0f - alpha) * (1.0f - alpha / alpha_prev);
        g_ncoef[s] = (t > 0) ? (sqrtf(fmaxf(sig2, 0.0f)) + 0.1f * fabsf(qi)) : 0.0f;
        unsigned o0, o1;
        tf2x32(0u, 1u, 0u, (unsigned)t, o0, o1);
        g_key[s][0] = o0; g_key[s][1] = o1;
    }
    if (s == STEPS) {
        unsigned o0, o1;
        tf2x32(0u, 1u, 0u, 10000u, o0, o1);
        g_key_init[0] = o0; g_key_init[1] = o1;
    }
    if (s == STEPS + 1) {
        unsigned k0, k1;
        tf2x32(0u, 1u, 0u, 99999u, k0, k1);
        unsigned b = tf_bits(k0, k1, 0u);
        g_u = __uint_as_float((b >> 9) | 0x3f800000u) - 1.0f;
    }
}

// ---------------------------------------------------------------------------
// Single merged weight transpose + fp16 convert (7 segments via blockIdx.y)
// ---------------------------------------------------------------------------
__global__ __launch_bounds__(256)
void wprep_all_kernel(const float* __restrict__ Wq,  const float* __restrict__ W01,
                      const float* __restrict__ W11, const float* __restrict__ W02,
                      const float* __restrict__ W12, const float* __restrict__ Wi1,
                      const float* __restrict__ Wi2) {
    int i = blockIdx.x * 256 + threadIdx.x;
    int seg = blockIdx.y;
    const float* src;
    __half* dst;
    int K, N;
    size_t dstoff = 0;
    switch (seg) {
        case 0: src = Wq;  dst = g_WqT;    K = FDIM; N = HDIM; break;
        case 1: src = W01; dst = g_W0111T; K = HDIM; N = HDIM; break;
        case 2: src = W11; dst = g_W0111T; K = HDIM; N = HDIM; dstoff = (size_t)HDIM * HDIM; break;
        case 3: src = W02; dst = g_W02T;   K = HDIM; N = FDIM; break;
        case 4: src = W12; dst = g_W12T;   K = HDIM; N = FDIM; break;
        case 5: src = Wi1; dst = g_Wi1T;   K = HDIM; N = HDIM; break;
        default: src = Wi2; dst = g_Wi2T;  K = HDIM; N = FDIM; break;
    }
    if (i >= K * N) return;
    int k = i / N, n = i - k * N;
    dst[dstoff + (size_t)n * K + k] = __float2half(src[i]);
}

// ---------------------------------------------------------------------------
// x0 init: normal + fp16 copy
// ---------------------------------------------------------------------------
__global__ __launch_bounds__(256) void init_kernel() {
    int j = blockIdx.x * 256 + threadIdx.x;
    float v = bits_to_normal(tf_bits(g_key_init[0], g_key_init[1], (unsigned)j));
    g_x[j] = v;
    g_xh[j] = __float2half(v);
}

// ---------------------------------------------------------------------------
// fp16 HMMA GEMM (mma.sync m16n8k16) — R10 proven schedule.
// C = act(A @ B^T + bias);  A [M,*] lda-strided, B [N,Ka] K-major.
// CTA 128x128, BK=64, 8 warps (2x4), warp tile 64x32; 2-stage cp.async,
// two syncs per chunk, 2 CTAs/SM.
// Dual-GEMM: gridDim.z==2 -> blockIdx.z==1 uses (A2, B2, bias2, col_off2).
// ACT: 0=none 1=relu 2=tanh 3=gelu 4=relu if n0<HDIM else tanh (bias2 = b11).
// OUTM: 0 = fp16 out, 3 = fused diffusion update (interf GEMM; writes x/xh).
// ---------------------------------------------------------------------------
#define SM_PITCH 144
#define SM_HALF  (128 * SM_PITCH)           // 18432
#define SM_STAGE (2 * SM_HALF)              // 36864
#define SMEM_TOTAL (2 * SM_STAGE)           // 73728

template <int ACT, int OUTM>
__global__ __launch_bounds__(256, 2)
void mm_kernel(const __half* __restrict__ A, int lda, int Ka,
               const __half* __restrict__ B,
               const float* __restrict__ bias, const float* __restrict__ bias2,
               __half* __restrict__ Ch, int ldc, int col_off,
               const __half* __restrict__ A2, const __half* __restrict__ B2,
               int col_off2, int step) {
    extern __shared__ char smem[];
    const uint32_t sb = smem_to_u32(smem);
    const int tid = threadIdx.x, lane = tid & 31, wid = tid >> 5;
    const int wr = wid >> 2, wc = wid & 3;            // warp grid 2x4
    const int m0 = blockIdx.y * 128, n0 = blockIdx.x * 128;
    const int NC = Ka / 64;

    if (blockIdx.z == 1) {        // dual-GEMM second problem
        A = A2; B = B2; bias = bias2; col_off = col_off2;
    }

    float acc[4][4][4];
#pragma unroll
    for (int i = 0; i < 4; i++)
#pragma unroll
        for (int j = 0; j < 4; j++)
#pragma unroll
            for (int q = 0; q < 4; q++) acc[i][j][q] = 0.0f;

    auto issue = [&](int c) {
        int k0 = c * 64;
        uint32_t so = sb + (c & 1) * SM_STAGE;
#pragma unroll
        for (int i = 0; i < 4; i++) {
            int idx = tid + i * 256;              // 0..1023
            int r = idx >> 3, cc = idx & 7;       // row, 16B chunk
            uint32_t d = so + r * SM_PITCH + cc * 16;
            cp16(d,           A + (size_t)(m0 + r) * lda + k0 + cc * 8);
            cp16(d + SM_HALF, B + (size_t)(n0 + r) * Ka  + k0 + cc * 8);
        }
        CP_COMMIT();
    };

    issue(0);
    if (NC > 1) issue(1);

    for (int c = 0; c < NC; c++) {
        if (c + 1 < NC) asm volatile("cp.async.wait_group 1;" ::: "memory");
        else            asm volatile("cp.async.wait_group 0;" ::: "memory");
        __syncthreads();

        uint32_t so = sb + (c & 1) * SM_STAGE;
#pragma unroll
        for (int ks = 0; ks < 4; ks++) {
            uint32_t ah[4][4];
            {
                int arow = wr * 64 + (lane & 15);
                uint32_t acol = (uint32_t)(ks * 16 + ((lane >> 4) << 3)) * 2;
#pragma unroll
                for (int mt = 0; mt < 4; mt++)
                    LDSM4(ah[mt], so + (uint32_t)(arow + mt * 16) * SM_PITCH + acol);
            }
            uint32_t bh[2][4];
            {
                int g = lane >> 3;
                int brow = wc * 32 + (lane & 7) + ((g >> 1) << 3);
                uint32_t bcol = (uint32_t)(ks * 16 + ((g & 1) << 3)) * 2;
#pragma unroll
                for (int p = 0; p < 2; p++)
                    LDSM4(bh[p], so + SM_HALF + (uint32_t)(brow + p * 16) * SM_PITCH + bcol);
            }
#pragma unroll
            for (int mt = 0; mt < 4; mt++)
#pragma unroll
                for (int nt = 0; nt < 4; nt++)
                    mma_f16(acc[mt][nt], ah[mt], &bh[nt >> 1][(nt & 1) * 2]);
        }
        __syncthreads();
        if (c + 2 < NC) issue(c + 2);
    }

    // ---- epilogue ----------------------------------------------------------
    if (OUTM == 3) {
        // interf tile = acc + bias; fused diffusion update of x (reads cath).
        const float sp0 = g_sp0, sp1 = g_sp1;
        const float qi = g_qi[step], cAv = g_cA[step];
        const float rsqa = g_rsqa[step], nc = g_ncoef[step];
        const unsigned kk0 = g_key[step][0], kk1 = g_key[step][1];
#pragma unroll
        for (int nt = 0; nt < 4; nt++) {
            int colg = n0 + wc * 32 + nt * 8 + (lane & 3) * 2;   // 0..511
            float b0 = bias[colg], b1 = bias[colg + 1];
#pragma unroll
            for (int mt = 0; mt < 4; mt++) {
                int rb = m0 + wr * 64 + mt * 16 + (lane >> 2);
#pragma unroll
                for (int h = 0; h < 2; h++) {
                    int r = rb + h * 8;
                    float i0 = acc[mt][nt][h * 2 + 0] + b0;
                    float i1 = acc[mt][nt][h * 2 + 1] + b1;
                    size_t cb = (size_t)r * HDIM + colg;
                    __half2 d0p = *(const __half2*)(g_cath + cb);
                    __half2 d1p = *(const __half2*)(g_cath + cb + 512);
                    float d0a = __low2float(d0p), d0b = __high2float(d0p);
                    float d1a = __low2float(d1p), d1b = __high2float(d1p);
                    int j = r * FDIM + colg;
                    float2 xv = *(float2*)(g_x + j);
                    float xn0 = (xv.x - cAv * (sp0 * d0a + sp1 * d1a + qi * i0)) * rsqa;
                    float xn1 = (xv.y - cAv * (sp0 * d0b + sp1 * d1b + qi * i1)) * rsqa;
                    if (nc != 0.0f) {
                        xn0 += nc * bits_to_normal(tf_bits(kk0, kk1, (unsigned)j));
                        xn1 += nc * bits_to_normal(tf_bits(kk0, kk1, (unsigned)(j + 1)));
                    }
                    *(float2*)(g_x + j) = make_float2(xn0, xn1);
                    *(__half2*)(g_xh + j) = __floats2half2_rn(xn0, xn1);
                }
            }
        }
    } else {
        const bool tanh_side = (ACT == 4) && (n0 >= HDIM);
        const float* bp = (ACT == 4 && tanh_side) ? bias2 : bias;
        const int colbase = (ACT == 4 && tanh_side) ? (n0 - HDIM) : n0;
#pragma unroll
        for (int nt = 0; nt < 4; nt++) {
            int coll = wc * 32 + nt * 8 + (lane & 3) * 2;
            int colg = n0 + coll;
            float b0 = bp[colbase + coll], b1 = bp[colbase + coll + 1];
#pragma unroll
            for (int mt = 0; mt < 4; mt++) {
                int r0 = m0 + wr * 64 + mt * 16 + (lane >> 2);
                float v[4];
                v[0] = acc[mt][nt][0] + b0;
                v[1] = acc[mt][nt][1] + b1;
                v[2] = acc[mt][nt][2] + b0;
                v[3] = acc[mt][nt][3] + b1;
#pragma unroll
                for (int q = 0; q < 4; q++) {
                    if (ACT == 1) v[q] = fmaxf(v[q], 0.0f);
                    else if (ACT == 2) v[q] = tanhf(v[q]);
                    else if (ACT == 3) v[q] = 0.5f * v[q] * (1.0f + erff(v[q] * 0.70710678f));
                    else if (ACT == 4) v[q] = tanh_side ? tanhf(v[q]) : fmaxf(v[q], 0.0f);
                }
                *(__half2*)(Ch + (size_t)r0 * ldc + col_off + colg) = __floats2half2_rn(v[0], v[1]);
                *(__half2*)(Ch + (size_t)(r0 + 8) * ldc + col_off + colg) = __floats2half2_rn(v[2], v[3]);
            }
        }
    }
}

// ---------------------------------------------------------------------------
// Measurement collapse
// ---------------------------------------------------------------------------
__global__ __launch_bounds__(256) void final_kernel(const float* __restrict__ real,
                                                    float* __restrict__ out) {
    int i = blockIdx.x * 256 + threadIdx.x;
    float x = g_x[i];
    out[i] = (g_u < g_p0) ? (0.7f * x + 0.3f * real[i]) : x;
}

// ---------------------------------------------------------------------------
// Launch
// ---------------------------------------------------------------------------
extern "C" void kernel_launch(void* const* d_in, const int* in_sizes, int n_in,
                              void* d_out, int out_size) {
    const float *real, *Wq, *bq, *W01, *b01, *W02, *b02, *W11, *b11;
    const float *W12, *b12, *Wi1, *bi1, *Wi2, *bi2, *a_amp, *b_amp, *pc;

    if (in_sizes[0] == NELEM) {
        int o = (n_in >= 2 && in_sizes[1] == 1) ? 2 : 1;
        real = (const float*)d_in[0];
        Wq   = (const float*)d_in[o + 0];  bq  = (const float*)d_in[o + 1];
        W01  = (const float*)d_in[o + 2];  b01 = (const float*)d_in[o + 3];
        W02  = (const float*)d_in[o + 4];  b02 = (const float*)d_in[o + 5];
        W11  = (const float*)d_in[o + 6];  b11 = (const float*)d_in[o + 7];
        W12  = (const float*)d_in[o + 8];  b12 = (const float*)d_in[o + 9];
        Wi1  = (const float*)d_in[o + 10]; bi1 = (const float*)d_in[o + 11];
        Wi2  = (const float*)d_in[o + 12]; bi2 = (const float*)d_in[o + 13];
        a_amp = (const float*)d_in[o + 14];
        b_amp = (const float*)d_in[o + 15];
        pc    = (const float*)d_in[o + 16];
    } else {
        W01 = (const float*)d_in[0];  W02 = (const float*)d_in[1];
        W11 = (const float*)d_in[2];  W12 = (const float*)d_in[3];
        Wi1 = (const float*)d_in[4];  Wi2 = (const float*)d_in[5];
        Wq  = (const float*)d_in[6];  a_amp = (const float*)d_in[7];
        b01 = (const float*)d_in[8];  b02 = (const float*)d_in[9];
        b11 = (const float*)d_in[10]; b12 = (const float*)d_in[11];
        b_amp = (const float*)d_in[12];
        bi1 = (const float*)d_in[13]; bi2 = (const float*)d_in[14];
        bq  = (const float*)d_in[15]; pc  = (const float*)d_in[16];
        real = (const float*)d_in[17];
    }
    float* out = (float*)d_out;

    void *p;
    #define SYMH(var, sym) cudaGetSymbolAddress(&p, sym); auto* var = (__half*)p;
    SYMH(xh, g_xh)
    SYMH(qfh, g_qfh)
    SYMH(h01, g_h01)
    SYMH(hh, g_hh)
    SYMH(cath, g_cath)
    SYMH(WqT, g_WqT)
    SYMH(W0111T, g_W0111T)
    SYMH(W02T, g_W02T)
    SYMH(W12T, g_W12T)
    SYMH(Wi1T, g_Wi1T)
    SYMH(Wi2T, g_Wi2T)
    #undef SYMH

    cudaFuncSetAttribute(mm_kernel<1, 0>, cudaFuncAttributeMaxDynamicSharedMemorySize, SMEM_TOTAL);
    cudaFuncSetAttribute(mm_kernel<4, 0>, cudaFuncAttributeMaxDynamicSharedMemorySize, SMEM_TOTAL);
    cudaFuncSetAttribute(mm_kernel<0, 0>, cudaFuncAttributeMaxDynamicSharedMemorySize, SMEM_TOTAL);
    cudaFuncSetAttribute(mm_kernel<3, 0>, cudaFuncAttributeMaxDynamicSharedMemorySize, SMEM_TOTAL);
    cudaFuncSetAttribute(mm_kernel<0, 3>, cudaFuncAttributeMaxDynamicSharedMemorySize, SMEM_TOTAL);

    prep_kernel<<<1, 64>>>(a_amp, b_amp, pc);
    init_kernel<<<NELEM / 256, 256>>>();
    wprep_all_kernel<<<dim3(4096, 7), 256>>>(Wq, W01, W11, W02, W12, Wi1, Wi2);

    dim3 gH(HDIM / 128, NROWS / 128);          // (8, 64)
    dim3 gH2(2 * HDIM / 128, NROWS / 128);     // (16, 64) fused h01
    dim3 gFz(FDIM / 128, NROWS / 128, 2);      // (4, 64, 2) dual d0/d1
    dim3 gF(FDIM / 128, NROWS / 128);          // (4, 64)

    for (int s = 0; s < STEPS; s++) {
        // qf = relu(x @ Wq + bq)
        mm_kernel<1, 0><<<gH, 256, SMEM_TOTAL>>>(xh, FDIM, FDIM, WqT, bq, bq,
                                                 qfh, HDIM, 0,
                                                 nullptr, nullptr, 0, 0);
        // [h0|h1] = {relu|tanh}(qf @ [W01;W11]^T + {b01|b11})
        mm_kernel<4, 0><<<gH2, 256, SMEM_TOTAL>>>(qfh, HDIM, HDIM, W0111T, b01, b11,
                                                  h01, 2 * HDIM, 0,
                                                  nullptr, nullptr, 0, 0);
        // dual: z=0 -> d0 = h0 @ W02 + b02 -> cat[:,0:512]
        //       z=1 -> d1 = h1 @ W12 + b12 -> cat[:,512:1024]
        mm_kernel<0, 0><<<gFz, 256, SMEM_TOTAL>>>(h01, 2 * HDIM, HDIM, W02T, b02, b12,
                                                  cath, HDIM, 0,
                                                  h01 + HDIM, W12T, FDIM, 0);
        // hg = gelu(cat @ Wi1 + bi1)
        mm_kernel<3, 0><<<gH, 256, SMEM_TOTAL>>>(cath, HDIM, HDIM, Wi1T, bi1, bi1,
                                                 hh, HDIM, 0,
                                                 nullptr, nullptr, 0, 0);
        // interf GEMM + FUSED diffusion update (writes g_x / g_xh)
        mm_kernel<0, 3><<<gF, 256, SMEM_TOTAL>>>(hh, HDIM, HDIM, Wi2T, bi2, bi2,
                                                 nullptr, FDIM, 0,
                                                 nullptr, nullptr, 0, s);
    }

    final_kernel<<<NELEM / 256, 256>>>(real, out);
}